// round 3
// baseline (speedup 1.0000x reference)
#include <cuda_runtime.h>
#include <utility>

// =====================================================================
// HiPPO-LegS reconstruction:  out = sum_{k=1..256} coef[k-1]*sqrt(2k+1)*P_k(x),
// x = 2*t/curr_t - 1, evaluated at 524288 points.
//
// Scaled Clenshaw backward recurrence with compile-time constants so every
// step is   t  = FFMA(b2, -beta_imm, c)   (imm form, rt_SMSP=1)
//           b0 = FFMA(b1, x, t)           (reg form, rt_SMSP=2)
// = 3 fma-pipe issue cycles per element-step. Power-of-two rescales keep
// fp32 in range. V=8 elements/thread for ILP + LDS amortization.
// Template recursion is chunked (16 steps per level via pack expansion)
// to stay under nvcc's instantiation depth limit.
// =====================================================================

#define NDEG 256
#define V    8
#define TPB  256

// ---------------- compile-time scaling machinery ----------------

__host__ __device__ constexpr double c_TH()  { return 9.5367431640625e-07; } // 2^-20
__host__ __device__ constexpr double c_RHO() { return 1048576.0; }           // 2^20

__host__ __device__ constexpr double Ak(int k) { return (2.0 * k + 1.0) / (double)(k + 1); }
__host__ __device__ constexpr double Bk(int k) { return (double)k / (double)(k + 1); }

// s_{257} = s_{258} = 1; going down: s_k = s_{k+1}/A_k, boosted by RHO when < TH.
__host__ __device__ constexpr double s_of(int k) {
    if (k >= NDEG + 1) return 1.0;
    double s = 1.0;
    for (int j = NDEG; j >= k; --j) {
        s /= Ak(j);
        if (s < c_TH()) s *= c_RHO();
    }
    return s;
}

__host__ __device__ constexpr bool boosted(int k) {
    if (k >= NDEG + 1) return false;
    double s = 1.0;
    for (int j = NDEG; j >= k; --j) {
        s /= Ak(j);
        if (s < c_TH()) {
            s *= c_RHO();
            if (j == k) return true;
        }
    }
    return false;
}

// beta_k = B_{k+1} * s_k / s_{k+2}   (multiplies b~_{k+2})
__host__ __device__ constexpr double beta_of(int k) {
    return Bk(k + 1) * s_of(k) / s_of(k + 2);
}

// constexpr sqrt (Newton, double)
__host__ __device__ constexpr double csqrt(double v) {
    double g = v < 1.0 ? 1.0 : v;
    for (int i = 0; i < 100; ++i) g = 0.5 * (g + v / g);
    return g;
}

// g_k = s_k * sqrt(2k+1): folded scale for the runtime coefficient c_k
__host__ __device__ constexpr float g_of(int k) {
    return (float)(s_of(k) * csqrt(2.0 * k + 1.0));
}

struct GTab { float v[NDEG + 1]; };
template <size_t... I>
constexpr GTab make_gtab(std::index_sequence<I...>) {
    return GTab{{ (I == 0 ? 0.0f : g_of((int)I))... }};
}
__constant__ GTab G = make_gtab(std::make_index_sequence<NDEG + 1>{});

// ---------------- Clenshaw steps, chunked template expansion ----------------
// Invariant entering step K:  b1[v] = s_{K+1}*b_{K+1},  b2[v] = s_{K+2}*b_{K+2}

template <int K>
__device__ __forceinline__ void one_step(const float (&sc)[NDEG + 1],
                                         const float (&x)[V],
                                         float (&b1)[V], float (&b2)[V]) {
    constexpr float BETA  = (float)(-beta_of(K));  // immediate multiplier
    constexpr bool  BOOST = boosted(K);
    const float c = sc[K];                          // LDS broadcast
#pragma unroll
    for (int v = 0; v < V; ++v) {
        float o1  = b1[v];
        float bb1 = o1;
        if constexpr (BOOST) bb1 = o1 * (float)c_RHO();  // rare pow2 rescale
        float tt = fmaf(b2[v], BETA, c);            // FFMA imm  (rt=1)
        b1[v]    = fmaf(bb1, x[v], tt);             // FFMA reg  (rt=2)
        b2[v]    = o1;                              // rotate (register rename)
    }
}

// Expand CH steps K, K-1, ..., K-CH+1 via pack expansion (no recursion depth).
template <int K, size_t... J>
__device__ __forceinline__ void chunk_steps(std::index_sequence<J...>,
                                            const float (&sc)[NDEG + 1],
                                            const float (&x)[V],
                                            float (&b1)[V], float (&b2)[V]) {
    (one_step<K - (int)J>(sc, x, b1, b2), ...);
}

template <int K>
struct Step {
    static constexpr int CH = (K + 1 < 16) ? (K + 1) : 16;
    static __device__ __forceinline__ void run(const float (&sc)[NDEG + 1],
                                               const float (&x)[V],
                                               float (&b1)[V], float (&b2)[V]) {
        chunk_steps<K>(std::make_index_sequence<CH>{}, sc, x, b1, b2);
        Step<K - CH>::run(sc, x, b1, b2);
    }
};
template <>
struct Step<-1> {
    static __device__ __forceinline__ void run(const float (&)[NDEG + 1],
                                               const float (&)[V],
                                               float (&)[V], float (&)[V]) {}
};

// ---------------- kernel ----------------

__global__ __launch_bounds__(TPB) void hippo_clenshaw_kernel(
    const float* __restrict__ t, const float* __restrict__ coef,
    const int* __restrict__ ctp, float* __restrict__ out, int n)
{
    __shared__ float sc[NDEG + 1];
    for (int i = threadIdx.x; i <= NDEG; i += TPB)
        sc[i] = (i == 0) ? 0.0f : G.v[i] * __ldg(coef + i - 1);
    __syncthreads();

    // curr_t: tolerate int32 payload (expected) or a float bit pattern
    float ct = 1.0f;
    if (ctp) {
        int iv   = *ctp;
        float fv = __int_as_float(iv);
        ct = (iv > 0 && iv < (1 << 20)) ? (float)iv : fv;
    }
    const float sc2 = 2.0f / ct;

    const long long base = ((long long)blockIdx.x * TPB + threadIdx.x) * V;
    if (base >= n) return;

    constexpr float INVS0 = (float)(1.0 / s_of(0));

    if (base + V <= n) {
        // fast path: 2x LDG.128, fully coalesced
        float4 ta = *reinterpret_cast<const float4*>(t + base);
        float4 tb = *reinterpret_cast<const float4*>(t + base + 4);
        float tv[V] = {ta.x, ta.y, ta.z, ta.w, tb.x, tb.y, tb.z, tb.w};
        float x[V], b1[V], b2[V];
#pragma unroll
        for (int v = 0; v < V; ++v) {
            x[v]  = fmaf(tv[v], sc2, -1.0f);
            b1[v] = 0.0f;
            b2[v] = 0.0f;
        }
        Step<NDEG>::run(sc, x, b1, b2);
        float4 oa = make_float4(b1[0] * INVS0, b1[1] * INVS0,
                                b1[2] * INVS0, b1[3] * INVS0);
        float4 ob = make_float4(b1[4] * INVS0, b1[5] * INVS0,
                                b1[6] * INVS0, b1[7] * INVS0);
        *reinterpret_cast<float4*>(out + base)     = oa;
        *reinterpret_cast<float4*>(out + base + 4) = ob;
    } else {
        // tail path (not hit for 524288, kept for safety): clamped loads
        float x[V], b1[V], b2[V];
#pragma unroll
        for (int v = 0; v < V; ++v) {
            long long idx = base + v;
            float tv = (idx < n) ? t[idx] : 0.0f;
            x[v]  = fmaf(tv, sc2, -1.0f);
            b1[v] = 0.0f;
            b2[v] = 0.0f;
        }
        Step<NDEG>::run(sc, x, b1, b2);
#pragma unroll
        for (int v = 0; v < V; ++v) {
            long long idx = base + v;
            if (idx < n) out[idx] = b1[v] * INVS0;
        }
    }
}

// ---------------- launch ----------------

extern "C" void kernel_launch(void* const* d_in, const int* in_sizes, int n_in,
                              void* d_out, int out_size)
{
    // Identify inputs by size: big -> t, 1 -> curr_t, remaining -> coef
    int ti = -1, ci = -1, si = -1;
    for (int i = 0; i < n_in; ++i) {
        if (in_sizes[i] == out_size && ti < 0)      ti = i;
        else if (in_sizes[i] == 1 && si < 0)        si = i;
        else if (ci < 0)                            ci = i;
    }
    if (ti < 0) ti = 0;
    if (ci < 0) ci = (n_in > 1 ? 1 : 0);

    const float* t    = (const float*)d_in[ti];
    const float* coef = (const float*)d_in[ci];
    const int*   ct   = (si >= 0) ? (const int*)d_in[si] : nullptr;

    int n = out_size;
    int elems_per_block = TPB * V;
    int blocks = (n + elems_per_block - 1) / elems_per_block;
    hippo_clenshaw_kernel<<<blocks, TPB>>>(t, coef, ct, (float*)d_out, n);
}